// round 1
// baseline (speedup 1.0000x reference)
#include <cuda_runtime.h>
#include <math.h>

#define NN 100000
#define EE 3200000
#define FIN 37
#define HID 16
#define NCLS 2

// ---- scratch (static __device__ allocation; re-initialized every call) ----
__device__ float  g_deg [NN];
__device__ float  g_dinv[NN];
__device__ float4 g_hs1 [NN * 4];   // dinv * (x @ W1), 16 floats per node
__device__ float4 g_acc1[NN * 4];   // scatter accumulator, layer 1
__device__ float2 g_hs2 [NN];       // dinv * (relu_out @ W2)
__device__ float2 g_acc2[NN];       // scatter accumulator, layer 2

// ---- K0: reset scratch ----
__global__ void k_init() {
    int i = blockIdx.x * blockDim.x + threadIdx.x;
    if (i < NN * 4) g_acc1[i] = make_float4(0.f, 0.f, 0.f, 0.f);
    if (i < NN) {
        g_acc2[i] = make_float2(0.f, 0.f);
        g_deg[i]  = 1.0f;            // self-loop weight
    }
}

// ---- K1: degree accumulation over edge targets ----
__global__ void k_deg(const int* __restrict__ col, const float* __restrict__ w) {
    int e = blockIdx.x * blockDim.x + threadIdx.x;
    if (e < EE) atomicAdd(&g_deg[__ldg(&col[e])], __ldg(&w[e]));
}

// ---- K2: dinv + hs1 = dinv * (x @ W1) ----
__global__ void k_hs1(const float* __restrict__ x, const float* __restrict__ W1) {
    __shared__ float Ws[FIN * HID];
    for (int t = threadIdx.x; t < FIN * HID; t += blockDim.x) Ws[t] = W1[t];
    __syncthreads();
    int i = blockIdx.x * blockDim.x + threadIdx.x;
    if (i >= NN) return;

    float acc[HID];
    #pragma unroll
    for (int j = 0; j < HID; j++) acc[j] = 0.f;

    const float* xi = x + (long)i * FIN;
    #pragma unroll
    for (int k = 0; k < FIN; k++) {
        float xv = xi[k];
        #pragma unroll
        for (int j = 0; j < HID; j++) acc[j] = fmaf(xv, Ws[k * HID + j], acc[j]);
    }

    float d = rsqrtf(g_deg[i]);      // deg >= 1 always (self-loop)
    g_dinv[i] = d;
    #pragma unroll
    for (int j = 0; j < HID; j++) acc[j] *= d;

    float4* o = &g_hs1[i * 4];
    o[0] = make_float4(acc[0],  acc[1],  acc[2],  acc[3]);
    o[1] = make_float4(acc[4],  acc[5],  acc[6],  acc[7]);
    o[2] = make_float4(acc[8],  acc[9],  acc[10], acc[11]);
    o[3] = make_float4(acc[12], acc[13], acc[14], acc[15]);
}

// ---- K3: layer-1 edge scatter: acc1[col] += w * hs1[row]  (red.v4, no return) ----
__global__ void k_scat1(const int* __restrict__ row, const int* __restrict__ col,
                        const float* __restrict__ w) {
    int e = blockIdx.x * blockDim.x + threadIdx.x;
    if (e >= EE) return;
    int   r  = __ldg(&row[e]);
    int   c  = __ldg(&col[e]);
    float we = __ldg(&w[e]);
    const float4* h   = &g_hs1[r * 4];
    float*        dst = (float*)&g_acc1[c * 4];
    #pragma unroll
    for (int q = 0; q < 4; q++) {
        float4 v = h[q];
        asm volatile("red.global.add.v4.f32 [%0], {%1, %2, %3, %4};"
                     :: "l"(dst + q * 4),
                        "f"(v.x * we), "f"(v.y * we), "f"(v.z * we), "f"(v.w * we)
                     : "memory");
    }
}

// ---- K4: finish layer 1 (bias + relu), then hs2 = dinv * (relu_out @ W2) ----
__global__ void k_layer2(const float* __restrict__ W2, const float* __restrict__ b1) {
    __shared__ float Ws[HID * NCLS];
    __shared__ float bs[HID];
    if (threadIdx.x < HID * NCLS) Ws[threadIdx.x] = W2[threadIdx.x];
    if (threadIdx.x < HID)        bs[threadIdx.x] = b1[threadIdx.x];
    __syncthreads();
    int i = blockIdx.x * blockDim.x + threadIdx.x;
    if (i >= NN) return;

    float d = g_dinv[i];
    const float4* a = &g_acc1[i * 4];
    const float4* h = &g_hs1[i * 4];
    float o[HID];
    #pragma unroll
    for (int q = 0; q < 4; q++) {
        float4 av = a[q], hv = h[q];
        o[q*4+0] = fmaxf(d * (av.x + hv.x) + bs[q*4+0], 0.f);
        o[q*4+1] = fmaxf(d * (av.y + hv.y) + bs[q*4+1], 0.f);
        o[q*4+2] = fmaxf(d * (av.z + hv.z) + bs[q*4+2], 0.f);
        o[q*4+3] = fmaxf(d * (av.w + hv.w) + bs[q*4+3], 0.f);
    }

    float z0 = 0.f, z1 = 0.f;
    #pragma unroll
    for (int j = 0; j < HID; j++) {
        z0 = fmaf(o[j], Ws[j * NCLS + 0], z0);
        z1 = fmaf(o[j], Ws[j * NCLS + 1], z1);
    }
    g_hs2[i] = make_float2(d * z0, d * z1);
}

// ---- K5: layer-2 edge scatter (red.v2) ----
__global__ void k_scat2(const int* __restrict__ row, const int* __restrict__ col,
                        const float* __restrict__ w) {
    int e = blockIdx.x * blockDim.x + threadIdx.x;
    if (e >= EE) return;
    int   r  = __ldg(&row[e]);
    int   c  = __ldg(&col[e]);
    float we = __ldg(&w[e]);
    float2 h = g_hs2[r];
    asm volatile("red.global.add.v2.f32 [%0], {%1, %2};"
                 :: "l"((float*)&g_acc2[c]), "f"(h.x * we), "f"(h.y * we)
                 : "memory");
}

// ---- K6: finish layer 2 + log_softmax ----
__global__ void k_final(const float* __restrict__ b2, float* __restrict__ out) {
    int i = blockIdx.x * blockDim.x + threadIdx.x;
    if (i >= NN) return;
    float  d = g_dinv[i];
    float2 a = g_acc2[i];
    float2 h = g_hs2[i];
    float z0 = d * (a.x + h.x) + b2[0];
    float z1 = d * (a.y + h.y) + b2[1];
    float m   = fmaxf(z0, z1);
    float lse = m + logf(expf(z0 - m) + expf(z1 - m));
    out[2 * i + 0] = z0 - lse;
    out[2 * i + 1] = z1 - lse;
}

extern "C" void kernel_launch(void* const* d_in, const int* in_sizes, int n_in,
                              void* d_out, int out_size) {
    const float* x   = (const float*)d_in[0];          // [N, 37]
    const int*   ei  = (const int*)  d_in[1];          // [2, E]
    const float* ew  = (const float*)d_in[2];          // [E]
    const float* W1  = (const float*)d_in[3];          // [37, 16]
    const float* b1  = (const float*)d_in[4];          // [16]
    const float* W2  = (const float*)d_in[5];          // [16, 2]
    const float* b2  = (const float*)d_in[6];          // [2]
    float* out = (float*)d_out;                        // [N, 2]

    const int* row = ei;        // edge_index[0] = source
    const int* col = ei + EE;   // edge_index[1] = target

    const int TB = 256;
    int gInit = (NN * 4 + TB - 1) / TB;
    int gEdge = (EE + TB - 1) / TB;
    int gNode = (NN + TB - 1) / TB;

    k_init  <<<gInit, TB>>>();
    k_deg   <<<gEdge, TB>>>(col, ew);
    k_hs1   <<<gNode, TB>>>(x, W1);
    k_scat1 <<<gEdge, TB>>>(row, col, ew);
    k_layer2<<<gNode, TB>>>(W2, b1);
    k_scat2 <<<gEdge, TB>>>(row, col, ew);
    k_final <<<gNode, TB>>>(b2, out);
}